// round 13
// baseline (speedup 1.0000x reference)
#include <cuda_runtime.h>
#include <cstdint>

// ---------------------------------------------------------------------------
// ONE persistent kernel, 444 blocks (3/SM x 148).
//   blocks 0..3  : performers — weight collapse chain + finalize -> g_TSC
//   blocks 4..443: workers — 4-5 tiles each, software-pipelined staging
// out[b] = sum_{n,p}(Agg^2)[n,p](x_p.t_n) + sum_n R[n] s_n + c1
// Chain: p1 = Wl3.wl4 ; q = Wl2.p1+wl4 ; M = Wl1.q+wl4
//        c0 = bl1.q + bl2.p1 + bl3.wl4 + bl4
//        v_n = W2@M_n ; t_n = W1@v_n ; s_n = b1.v_n ; c1 = c0 + sum_n b2.M_n
// All cross-block sync via monotonic counters (replay-safe, no resets).
// ---------------------------------------------------------------------------

__device__ float g_p1[256];
__device__ float g_q[256];
__device__ float g_M[256];
__device__ float g_TSC[61];   // T[56], s[4], c1
__device__ int   g_tick;      // block tickets -> epoch   (+gridDim per launch)
__device__ int   g_pbar;      // performer barrier        (+12 per launch)
__device__ int   g_done;      // finalize completions     (+1 per launch)

__device__ __forceinline__ void l2_prefetch(const void* p) {
    asm volatile("prefetch.global.L2 [%0];" :: "l"(p));
}
__device__ __forceinline__ void fma2(unsigned long long& d,
                                     unsigned long long a, unsigned long long b) {
    asm("fma.rn.f32x2 %0, %1, %2, %0;" : "+l"(d) : "l"(a), "l"(b));
}
__device__ __forceinline__ float unpack_sum(unsigned long long v) {
    float lo, hi;
    asm("mov.b64 {%0, %1}, %2;" : "=f"(lo), "=f"(hi) : "l"(v));
    return lo + hi;
}
__device__ __forceinline__ float warp_sum(float a) {
    #pragma unroll
    for (int o = 16; o > 0; o >>= 1) a += __shfl_xor_sync(0xFFFFFFFFu, a, o);
    return a;
}

#define TPB    128
#define NPERF  4

__global__ __launch_bounds__(TPB, 3)
void gcn_all(const float* __restrict__ x, const int* __restrict__ eidx,
             float* __restrict__ out, int ntile,
             const float* __restrict__ W1, const float* __restrict__ b1,
             const float* __restrict__ W2, const float* __restrict__ b2,
             const float* __restrict__ Wl1, const float* __restrict__ bl1,
             const float* __restrict__ Wl2, const float* __restrict__ bl2,
             const float* __restrict__ Wl3, const float* __restrict__ bl3,
             const float* __restrict__ wl4, const float* __restrict__ bl4)
{
    __shared__ float4 sx4[TPB * 15];   // 60 floats/sample (pad 56->60); block0 aliases scratch
    __shared__ int4   se4[TPB * 7];    // 28 ints/sample  (pad 24->28)
    __shared__ float  sT[64];
    __shared__ int    s_epoch;
    int tid = threadIdx.x, wid = tid >> 5, lane = tid & 31;

    if (tid == 0) s_epoch = atomicAdd(&g_tick, 1) / gridDim.x;
    __syncthreads();
    int epoch = s_epoch;

    // ==================== performers: blocks 0..3 ==========================
    if (blockIdx.x < NPERF) {
        // prefetch this block's later-stage weight rows + finalize weights
        {
            const char* wl2base = (const char*)(Wl2 + (size_t)blockIdx.x * 64 * 256);
            const char* wl1base = (const char*)(Wl1 + (size_t)blockIdx.x * 64 * 256);
            #pragma unroll
            for (int j = 0; j < 4; j++) {
                l2_prefetch(wl2base + (tid + 128 * j) * 128);
                l2_prefetch(wl1base + (tid + 128 * j) * 128);
            }
            if (blockIdx.x == 0) {
                l2_prefetch((const char*)W2 + tid * 128);
                l2_prefetch((const char*)W2 + (tid + 128) * 128);
                if (tid < 56) l2_prefetch((const char*)W1 + tid * 128);
            }
        }
        int rbase = blockIdx.x * 64 + wid * 16;

        // ---- stage 0: p1 = Wl3 . wl4
        {
            const float4* W4 = (const float4*)Wl3;
            float4 vb0 = ((const float4*)wl4)[lane];
            float4 vb1 = ((const float4*)wl4)[32 + lane];
            #pragma unroll
            for (int b = 0; b < 4; b++) {
                int r = rbase + b * 4;
                float s[4];
                #pragma unroll
                for (int j = 0; j < 4; j++) {
                    float4 a0 = W4[(size_t)(r + j) * 64 + lane];
                    float4 a1 = W4[(size_t)(r + j) * 64 + 32 + lane];
                    s[j] = a0.x*vb0.x + a0.y*vb0.y + a0.z*vb0.z + a0.w*vb0.w
                         + a1.x*vb1.x + a1.y*vb1.y + a1.z*vb1.z + a1.w*vb1.w;
                }
                #pragma unroll
                for (int j = 0; j < 4; j++) s[j] = warp_sum(s[j]);
                if (lane == 0)
                    #pragma unroll
                    for (int j = 0; j < 4; j++) g_p1[r + j] = s[j];
            }
        }
        // performer barrier 0
        __threadfence(); __syncthreads();
        if (tid == 0) {
            atomicAdd(&g_pbar, 1);
            int tgt = epoch * 12 + 4;
            while ((*(volatile int*)&g_pbar) - tgt < 0) __nanosleep(32);
            __threadfence();
        }
        __syncthreads();

        // ---- stage 1: q = Wl2 . p1 + wl4
        {
            const float4* W4 = (const float4*)Wl2;
            float4 vb0 = __ldcg(((const float4*)g_p1) + lane);
            float4 vb1 = __ldcg(((const float4*)g_p1) + 32 + lane);
            #pragma unroll
            for (int b = 0; b < 4; b++) {
                int r = rbase + b * 4;
                float s[4];
                #pragma unroll
                for (int j = 0; j < 4; j++) {
                    float4 a0 = W4[(size_t)(r + j) * 64 + lane];
                    float4 a1 = W4[(size_t)(r + j) * 64 + 32 + lane];
                    s[j] = a0.x*vb0.x + a0.y*vb0.y + a0.z*vb0.z + a0.w*vb0.w
                         + a1.x*vb1.x + a1.y*vb1.y + a1.z*vb1.z + a1.w*vb1.w;
                }
                #pragma unroll
                for (int j = 0; j < 4; j++) s[j] = warp_sum(s[j]);
                if (lane == 0)
                    #pragma unroll
                    for (int j = 0; j < 4; j++) g_q[r + j] = s[j] + wl4[r + j];
            }
        }
        __threadfence(); __syncthreads();
        if (tid == 0) {
            atomicAdd(&g_pbar, 1);
            int tgt = epoch * 12 + 8;
            while ((*(volatile int*)&g_pbar) - tgt < 0) __nanosleep(32);
            __threadfence();
        }
        __syncthreads();

        // ---- stage 2: M = Wl1 . q + wl4
        {
            const float4* W4 = (const float4*)Wl1;
            float4 vb0 = __ldcg(((const float4*)g_q) + lane);
            float4 vb1 = __ldcg(((const float4*)g_q) + 32 + lane);
            #pragma unroll
            for (int b = 0; b < 4; b++) {
                int r = rbase + b * 4;
                float s[4];
                #pragma unroll
                for (int j = 0; j < 4; j++) {
                    float4 a0 = W4[(size_t)(r + j) * 64 + lane];
                    float4 a1 = W4[(size_t)(r + j) * 64 + 32 + lane];
                    s[j] = a0.x*vb0.x + a0.y*vb0.y + a0.z*vb0.z + a0.w*vb0.w
                         + a1.x*vb1.x + a1.y*vb1.y + a1.z*vb1.z + a1.w*vb1.w;
                }
                #pragma unroll
                for (int j = 0; j < 4; j++) s[j] = warp_sum(s[j]);
                if (lane == 0)
                    #pragma unroll
                    for (int j = 0; j < 4; j++) g_M[r + j] = s[j] + wl4[r + j];
            }
        }
        __threadfence(); __syncthreads();
        if (tid == 0) {
            atomicAdd(&g_pbar, 1);
            int tgt = epoch * 12 + 12;
            while ((*(volatile int*)&g_pbar) - tgt < 0) __nanosleep(32);
            __threadfence();
        }
        __syncthreads();

        if (blockIdx.x != 0) return;

        // ---- finalize (block 0, 128 threads; scratch aliased into sx4)
        float* sM   = (float*)sx4;        // 256
        float* sV   = sM + 256;           // 512
        float* sRed = sV + 512;           // 4
        sM[tid]       = __ldcg(g_M + tid);
        sM[tid + 128] = __ldcg(g_M + tid + 128);
        float contrib = bl1[tid] * __ldcg(g_q + tid) + bl2[tid] * __ldcg(g_p1 + tid)
                      + bl3[tid] * wl4[tid]
                      + bl1[tid+128] * __ldcg(g_q + tid+128)
                      + bl2[tid+128] * __ldcg(g_p1 + tid+128)
                      + bl3[tid+128] * wl4[tid+128];
        __syncthreads();
        if (tid < 64)
            contrib += b2[tid] * (sM[tid] + sM[64+tid] + sM[128+tid] + sM[192+tid]);
        contrib = warp_sum(contrib);
        if (lane == 0) sRed[wid] = contrib;
        #pragma unroll
        for (int rep = 0; rep < 4; rep++) {
            int o = tid + rep * 128;
            int n = o >> 7, k = o & 127;
            const float4* w4 = (const float4*)(W2 + (size_t)k * 64);
            const float4* m4 = (const float4*)(sM + n * 64);
            float a = 0.f;
            #pragma unroll
            for (int j = 0; j < 16; j++) {
                float4 w = w4[j], mm = m4[j];
                a += w.x * mm.x + w.y * mm.y + w.z * mm.z + w.w * mm.w;
            }
            sV[o] = a;
        }
        __syncthreads();
        for (int j = 0; j < 16; j++) {
            int rr = wid * 16 + j;
            if (rr < 60) {
                int nn = (rr < 56) ? (rr / 14) : (rr - 56);
                float4 w = (rr < 56)
                    ? ((const float4*)(W1 + (size_t)(rr % 14) * 128))[lane]
                    : ((const float4*)b1)[lane];
                float4 vv = ((const float4*)(sV + nn * 128))[lane];
                float a = w.x*vv.x + w.y*vv.y + w.z*vv.z + w.w*vv.w;
                a = warp_sum(a);
                if (lane == 0) g_TSC[rr] = a;
            } else if (rr == 60 && lane == 0) {
                g_TSC[60] = bl4[0] + sRed[0] + sRed[1] + sRed[2] + sRed[3];
            }
        }
        __threadfence(); __syncthreads();
        if (tid == 0) atomicAdd(&g_done, 1);
        return;
    }

    // ==================== workers: blocks 4..gridDim-1 ======================
    int wstride = gridDim.x - NPERF;
    int tile = blockIdx.x - NPERF;
    if (tile >= ntile) return;

    const float4* X4 = (const float4*)x;
    const int4*   E4 = (const int4*)eidx;
    float4 xv[14];
    int4   ev[6];

    // burst tile 0 (full MLP=20)
    {
        const float4* Xg = X4 + (size_t)tile * TPB * 14;
        const int4*   Eg = E4 + (size_t)tile * TPB * 6;
        #pragma unroll
        for (int i = 0; i < 14; i++) xv[i] = Xg[i * TPB + tid];
        #pragma unroll
        for (int i = 0; i < 6; i++)  ev[i] = Eg[i * TPB + tid];
    }

    float acc;
    bool first = true;
    while (true) {
        // ---- STS current tile
        #pragma unroll
        for (int i = 0; i < 14; i++) {
            int idx4 = i * TPB + tid;
            int s = idx4 / 14, j = idx4 % 14;
            sx4[s * 15 + j] = xv[i];
        }
        #pragma unroll
        for (int i = 0; i < 6; i++) {
            int i4 = i * TPB + tid;
            int s = i4 / 6, r = i4 % 6;
            se4[s * 7 + r] = ev[i];
        }
        __syncthreads();

        // ---- A2 / R from edges
        const int4* me4 = se4 + tid * 7;
        int4 f0 = me4[0], f1 = me4[1], f2 = me4[2];
        int4 f3 = me4[3], f4 = me4[4], f5 = me4[5];
        int es[12] = {f0.x,f0.y,f0.z,f0.w, f1.x,f1.y,f1.z,f1.w, f2.x,f2.y,f2.z,f2.w};
        int ed[12] = {f3.x,f3.y,f3.z,f3.w, f4.x,f4.y,f4.z,f4.w, f5.x,f5.y,f5.z,f5.w};
        unsigned h0 = 1u + (1u << 20);         // self loops: codes 0, 5
        unsigned h1 = (1u << 8) + (1u << 28);  // codes 10, 15
        #pragma unroll
        for (int e = 0; e < 12; e++) {
            int code = (ed[e] << 2) | es[e];
            unsigned inc = 1u << ((code & 7) << 2);
            if (code & 8) h1 += inc; else h0 += inc;
        }
        float c[16];
        #pragma unroll
        for (int qd = 0; qd < 8; qd++) {
            c[qd]     = (float)((h0 >> (qd * 4)) & 15u);
            c[qd + 8] = (float)((h1 >> (qd * 4)) & 15u);
        }
        float dinv[4];
        #pragma unroll
        for (int dd = 0; dd < 4; dd++)
            dinv[dd] = rsqrtf(c[4*dd] + c[4*dd+1] + c[4*dd+2] + c[4*dd+3]);
        float A[16];
        #pragma unroll
        for (int dd = 0; dd < 4; dd++)
            #pragma unroll
            for (int ss = 0; ss < 4; ss++)
                A[dd*4+ss] = c[dd*4+ss] * dinv[dd] * dinv[ss];
        float A2[16], R[4];
        #pragma unroll
        for (int n = 0; n < 4; n++) {
            R[n] = A[n*4] + A[n*4+1] + A[n*4+2] + A[n*4+3];
            #pragma unroll
            for (int p = 0; p < 4; p++) {
                A2[n*4+p] = A[n*4+0] * A[0*4+p] + A[n*4+1] * A[1*4+p]
                          + A[n*4+2] * A[2*4+p] + A[n*4+3] * A[3*4+p];
            }
        }

        // ---- burst NEXT tile (overlaps d2 compute below)
        int next = tile + wstride;
        if (next < ntile) {
            const float4* Xg = X4 + (size_t)next * TPB * 14;
            const int4*   Eg = E4 + (size_t)next * TPB * 6;
            #pragma unroll
            for (int i = 0; i < 14; i++) xv[i] = Xg[i * TPB + tid];
            #pragma unroll
            for (int i = 0; i < 6; i++)  ev[i] = Eg[i * TPB + tid];
        }

        // ---- one-time wait for TSC (overlapped with first burst + A2)
        if (first) {
            if (tid == 0) {
                while ((*(volatile int*)&g_done) - (epoch + 1) < 0) __nanosleep(64);
                __threadfence();
            }
            __syncthreads();
            if (tid < 61) sT[tid] = __ldcg(g_TSC + tid);
            __syncthreads();
            first = false;
        }

        // ---- d2[p*4+n] = x_p . t_n (packed f32x2, x pairs straight from smem)
        const float* mxf = (const float*)(sx4 + tid * 15);
        unsigned long long d2[16];
        #pragma unroll
        for (int i = 0; i < 16; i++) d2[i] = 0ULL;
        #pragma unroll
        for (int q = 0; q < 7; q++) {
            unsigned long long xp[4], tp[4];
            #pragma unroll
            for (int p = 0; p < 4; p++)
                xp[p] = *(const unsigned long long*)(mxf + p * 14 + 2 * q);
            #pragma unroll
            for (int n = 0; n < 4; n++)
                tp[n] = *(const unsigned long long*)(sT + n * 14 + 2 * q);
            #pragma unroll
            for (int p = 0; p < 4; p++)
                #pragma unroll
                for (int n = 0; n < 4; n++)
                    fma2(d2[p*4+n], xp[p], tp[n]);
        }
        acc = sT[60] + R[0]*sT[56] + R[1]*sT[57] + R[2]*sT[58] + R[3]*sT[59];
        #pragma unroll
        for (int n = 0; n < 4; n++)
            #pragma unroll
            for (int p = 0; p < 4; p++)
                acc += A2[n*4+p] * unpack_sum(d2[p*4+n]);
        out[tile * TPB + tid] = acc;

        if (next >= ntile) break;
        tile = next;
        __syncthreads();   // smem reads done before next STS
    }
}

extern "C" void kernel_launch(void* const* d_in, const int* in_sizes, int n_in,
                              void* d_out, int out_size)
{
    const float* x   = (const float*)d_in[0];
    const int*   ei  = (const int*)  d_in[1];
    const float* W1  = (const float*)d_in[2];
    const float* b1  = (const float*)d_in[3];
    const float* W2  = (const float*)d_in[4];
    const float* b2  = (const float*)d_in[5];
    const float* Wl1 = (const float*)d_in[6];
    const float* bl1 = (const float*)d_in[7];
    const float* Wl2 = (const float*)d_in[8];
    const float* bl2 = (const float*)d_in[9];
    const float* Wl3 = (const float*)d_in[10];
    const float* bl3 = (const float*)d_in[11];
    const float* wl4 = (const float*)d_in[12];
    const float* bl4 = (const float*)d_in[13];

    int B = in_sizes[0] / 56;   // 262144
    int ntile = B / TPB;        // 2048
    int grid = 444;             // 3 blocks/SM x 148 SMs; 4 performers + 440 workers

    gcn_all<<<grid, TPB>>>(x, ei, (float*)d_out, ntile,
                           W1, b1, W2, b2, Wl1, bl1, Wl2, bl2,
                           Wl3, bl3, wl4, bl4);
}

// round 14
// speedup vs baseline: 1.2881x; 1.2881x over previous
#include <cuda_runtime.h>
#include <cstdint>

// ---------------------------------------------------------------------------
// out[b] = sum_{n,p} (Agg_b^2)[n,p] * (x_b[p] . t_n)
//        + sum_n rowsum(Agg_b)[n] * s_n  +  c1
//
// Precompute (all row-pattern matvecs):
//   p1 = Wl3 . wl4
//   q  = Wl2 . p1 + wl4
//   M  = Wl1 . q  + wl4
//   c0 = bl1.q + bl2.p1 + bl3.wl4 + bl4
//   v_n = W2 @ M_n ; t_n = W1 @ v_n ; s_n = b1.v_n ; c1 = c0 + sum_n b2.M_n
// ---------------------------------------------------------------------------

__device__ float g_p1[256];
__device__ float g_q[256];
__device__ float g_M[256];
__device__ float g_TSC[61];   // T[56], s[4], c1

// ---- warp-per-row 256x256 matvec; globals selected BY SYMBOL in device code
__global__ void matvec256(const float* __restrict__ W, const float* __restrict__ extv,
                          const float* __restrict__ addv, int stage)
{
    const float* v = (stage == 0) ? extv : (stage == 1 ? g_p1 : g_q);
    float* outv    = (stage == 0) ? g_p1 : (stage == 1 ? g_q  : g_M);
    int warp = threadIdx.x >> 5, lane = threadIdx.x & 31;
    int r = blockIdx.x * 8 + warp;
    const float* row = W + (size_t)r * 256;
    float a = 0.f;
    #pragma unroll
    for (int k = 0; k < 8; k++) a += row[lane + 32 * k] * v[lane + 32 * k];
    #pragma unroll
    for (int o = 16; o > 0; o >>= 1) a += __shfl_xor_sync(0xFFFFFFFFu, a, o);
    if (lane == 0) outv[r] = a + (addv ? addv[r] : 0.f);
}

// ---- finalize: latency-optimized single block, 512 threads
__global__ __launch_bounds__(512)
void finalize(const float* __restrict__ W1, const float* __restrict__ b1,
              const float* __restrict__ W2, const float* __restrict__ b2,
              const float* __restrict__ bl1, const float* __restrict__ bl2,
              const float* __restrict__ bl3, const float* __restrict__ wl4,
              const float* __restrict__ bl4)
{
    __shared__ float sM[256];
    __shared__ float sV[512];
    __shared__ float sRed[16];
    int t = threadIdx.x;
    int wid = t >> 5, lane = t & 31;

    int n = t >> 7, k = t & 127;

    // Issue W2 row loads immediately (16 independent LDG.128)
    float4 w[16];
    const float4* w4 = (const float4*)(W2 + (size_t)k * 64);
    #pragma unroll
    for (int j = 0; j < 16; j++) w[j] = w4[j];

    float contrib = 0.f;
    if (t < 256) {
        sM[t] = g_M[t];
        contrib = bl1[t] * g_q[t] + bl2[t] * g_p1[t] + bl3[t] * wl4[t];
    }
    __syncthreads();
    if (t < 64)
        contrib += b2[t] * (sM[t] + sM[64 + t] + sM[128 + t] + sM[192 + t]);
    #pragma unroll
    for (int o = 16; o > 0; o >>= 1) contrib += __shfl_xor_sync(0xFFFFFFFFu, contrib, o);
    if (lane == 0) sRed[wid] = contrib;

    // V[o] = W2[k,:] . M_n
    {
        const float4* m4 = (const float4*)(sM + n * 64);
        float a = 0.f;
        #pragma unroll
        for (int j = 0; j < 16; j++) {
            float4 mm = m4[j];
            a += w[j].x * mm.x + w[j].y * mm.y + w[j].z * mm.z + w[j].w * mm.w;
        }
        sV[t] = a;
    }
    __syncthreads();

    // T/s/c1: warp-per-row, rows r = wid*4 + rep (0..63); 60 real rows + c1
    float4 wr[4];
    int rows[4];
    #pragma unroll
    for (int rep = 0; rep < 4; rep++) {
        int r = wid * 4 + rep;
        rows[rep] = r;
        if (r < 56) {
            int i = r % 14;
            wr[rep] = ((const float4*)(W1 + (size_t)i * 128))[lane];
        } else if (r < 60) {
            wr[rep] = ((const float4*)b1)[lane];
        } else {
            wr[rep] = make_float4(0.f, 0.f, 0.f, 0.f);
        }
    }
    #pragma unroll
    for (int rep = 0; rep < 4; rep++) {
        int r = rows[rep];
        if (r < 60) {
            int nn = (r < 56) ? (r / 14) : (r - 56);
            float4 vv = ((const float4*)(sV + nn * 128))[lane];
            float a = wr[rep].x * vv.x + wr[rep].y * vv.y
                    + wr[rep].z * vv.z + wr[rep].w * vv.w;
            #pragma unroll
            for (int o = 16; o > 0; o >>= 1) a += __shfl_xor_sync(0xFFFFFFFFu, a, o);
            if (lane == 0) g_TSC[r] = a;
        } else if (r == 60 && lane == 0) {
            float c = bl4[0];
            #pragma unroll
            for (int j = 0; j < 16; j++) c += sRed[j];
            g_TSC[60] = c;
        }
    }
}

// ---- packed f32x2 helpers (Blackwell FFMA2 path)
__device__ __forceinline__ unsigned long long pack2(float lo, float hi) {
    unsigned long long r;
    asm("mov.b64 %0, {%1, %2};" : "=l"(r) : "f"(lo), "f"(hi));
    return r;
}
__device__ __forceinline__ void fma2(unsigned long long& d,
                                     unsigned long long a, unsigned long long b) {
    asm("fma.rn.f32x2 %0, %1, %2, %0;" : "+l"(d) : "l"(a), "l"(b));
}
__device__ __forceinline__ float unpack_sum(unsigned long long v) {
    float lo, hi;
    asm("mov.b64 {%0, %1}, %2;" : "=f"(lo), "=f"(hi) : "l"(v));
    return lo + hi;
}

// ---- main kernel: cp.async staging (zero-register transpose-scatter)
#define TPB 128

__global__ __launch_bounds__(TPB, 5)
void gcn_main(const float* __restrict__ x, const int* __restrict__ eidx,
              float* __restrict__ out)
{
    __shared__ float4 sx4[TPB * 15];   // 60 floats/sample (pad 56->60)
    __shared__ int4   se4[TPB * 7];    // 28 ints/sample  (pad 24->28)
    __shared__ float  sT[64];
    int tid = threadIdx.x;

    const float4* Xg = (const float4*)x + (size_t)blockIdx.x * TPB * 14;
    const int4*   Eg = (const int4*)eidx + (size_t)blockIdx.x * TPB * 6;

    // ---- async stage: global -> shared, no register roundtrip, no STS
    #pragma unroll
    for (int i = 0; i < 14; i++) {
        int idx4 = i * TPB + tid;
        int s = idx4 / 14, j = idx4 % 14;
        unsigned dst = (unsigned)__cvta_generic_to_shared(&sx4[s * 15 + j]);
        asm volatile("cp.async.cg.shared.global [%0], [%1], 16;\n"
                     :: "r"(dst), "l"(Xg + idx4) : "memory");
    }
    #pragma unroll
    for (int i = 0; i < 6; i++) {
        int i4 = i * TPB + tid;
        int s = i4 / 6, r = i4 % 6;
        unsigned dst = (unsigned)__cvta_generic_to_shared(&se4[s * 7 + r]);
        asm volatile("cp.async.cg.shared.global [%0], [%1], 16;\n"
                     :: "r"(dst), "l"(Eg + i4) : "memory");
    }
    asm volatile("cp.async.commit_group;\n" ::: "memory");
    if (tid < 61) sT[tid] = g_TSC[tid];
    asm volatile("cp.async.wait_group 0;\n" ::: "memory");
    __syncthreads();

    // ---- edges: 6 LDS.128 (stride 112B, conflict-free), reg-only histogram
    const int4* me4 = se4 + tid * 7;
    int4 f0 = me4[0], f1 = me4[1], f2 = me4[2];
    int4 f3 = me4[3], f4 = me4[4], f5 = me4[5];
    int es[12] = {f0.x,f0.y,f0.z,f0.w, f1.x,f1.y,f1.z,f1.w, f2.x,f2.y,f2.z,f2.w};
    int ed[12] = {f3.x,f3.y,f3.z,f3.w, f4.x,f4.y,f4.z,f4.w, f5.x,f5.y,f5.z,f5.w};

    unsigned h0 = 1u + (1u << 20);         // self loops: codes 0, 5
    unsigned h1 = (1u << 8) + (1u << 28);  // codes 10, 15
    #pragma unroll
    for (int e = 0; e < 12; e++) {
        int code = (ed[e] << 2) | es[e];
        unsigned inc = 1u << ((code & 7) << 2);
        if (code & 8) h1 += inc; else h0 += inc;
    }
    float c[16];
    #pragma unroll
    for (int qd = 0; qd < 8; qd++) {
        c[qd]     = (float)((h0 >> (qd * 4)) & 15u);
        c[qd + 8] = (float)((h1 >> (qd * 4)) & 15u);
    }
    float dinv[4];
    #pragma unroll
    for (int d = 0; d < 4; d++)
        dinv[d] = rsqrtf(c[4*d] + c[4*d+1] + c[4*d+2] + c[4*d+3]);
    float A[16];
    #pragma unroll
    for (int d = 0; d < 4; d++)
        #pragma unroll
        for (int s = 0; s < 4; s++)
            A[d*4+s] = c[d*4+s] * dinv[d] * dinv[s];
    float A2[16], R[4];
    #pragma unroll
    for (int n = 0; n < 4; n++) {
        R[n] = A[n*4] + A[n*4+1] + A[n*4+2] + A[n*4+3];
        #pragma unroll
        for (int p = 0; p < 4; p++) {
            A2[n*4+p] = A[n*4+0] * A[0*4+p] + A[n*4+1] * A[1*4+p]
                      + A[n*4+2] * A[2*4+p] + A[n*4+3] * A[3*4+p];
        }
    }

    // ---- x: 14 LDS.128 (stride 240B, conflict-free)
    float4 mx4[14];
    const float4* mrow = sx4 + tid * 15;
    #pragma unroll
    for (int j = 0; j < 14; j++) mx4[j] = mrow[j];

    // ---- d2[p*4+n] = x_p . t_n over feature pairs, packed f32x2 FMA
    unsigned long long d2[16];
    #pragma unroll
    for (int i = 0; i < 16; i++) d2[i] = 0ULL;
    #pragma unroll
    for (int q = 0; q < 7; q++) {
        unsigned long long xp[4], tp[4];
        #pragma unroll
        for (int p = 0; p < 4; p++) {
            int off = p * 14 + 2 * q;            // always even -> pair within one float4
            float4 v = mx4[off >> 2];
            xp[p] = (off & 2) ? pack2(v.z, v.w) : pack2(v.x, v.y);
        }
        #pragma unroll
        for (int n = 0; n < 4; n++)
            tp[n] = *(const unsigned long long*)(sT + n * 14 + 2 * q);  // LDS.64 bcast
        #pragma unroll
        for (int p = 0; p < 4; p++)
            #pragma unroll
            for (int n = 0; n < 4; n++)
                fma2(d2[p*4+n], xp[p], tp[n]);
    }

    float acc = sT[60] + R[0]*sT[56] + R[1]*sT[57] + R[2]*sT[58] + R[3]*sT[59];
    #pragma unroll
    for (int n = 0; n < 4; n++)
        #pragma unroll
        for (int p = 0; p < 4; p++)
            acc += A2[n*4+p] * unpack_sum(d2[p*4+n]);

    out[blockIdx.x * TPB + tid] = acc;
}

extern "C" void kernel_launch(void* const* d_in, const int* in_sizes, int n_in,
                              void* d_out, int out_size)
{
    const float* x   = (const float*)d_in[0];
    const int*   ei  = (const int*)  d_in[1];
    const float* W1  = (const float*)d_in[2];
    const float* b1  = (const float*)d_in[3];
    const float* W2  = (const float*)d_in[4];
    const float* b2  = (const float*)d_in[5];
    const float* Wl1 = (const float*)d_in[6];
    const float* bl1 = (const float*)d_in[7];
    const float* Wl2 = (const float*)d_in[8];
    const float* bl2 = (const float*)d_in[9];
    const float* Wl3 = (const float*)d_in[10];
    const float* bl3 = (const float*)d_in[11];
    const float* wl4 = (const float*)d_in[12];
    const float* bl4 = (const float*)d_in[13];

    int B = in_sizes[0] / 56;   // 262144

    matvec256<<<32, 256>>>(Wl3, wl4, nullptr, 0);  // g_p1 = Wl3.wl4
    matvec256<<<32, 256>>>(Wl2, nullptr, wl4, 1);  // g_q  = Wl2.p1 + wl4
    matvec256<<<32, 256>>>(Wl1, nullptr, wl4, 2);  // g_M  = Wl1.q  + wl4
    finalize<<<1, 512>>>(W1, b1, W2, b2, bl1, bl2, bl3, wl4, bl4);
    gcn_main<<<B / TPB, TPB>>>(x, ei, (float*)d_out);
}